// round 15
// baseline (speedup 1.0000x reference)
#include <cuda_runtime.h>
#include <cuda_fp16.h>
#include <math_constants.h>

#define SEQ 4096
#define DH 64
#define NH 4
#define BM 64           // 4 warps x 16 rows
#define BN 128          // keys per tile
#define NTILES (SEQ / BN)              // 32
#define KPAD 72
#define TSZ (BN * KPAD)                // halves per stage (9216)
#define STAGE_B (TSZ * 2)              // 18432 B
#define SMEM_BYTES (4 * STAGE_B)       // 2 K + 2 V stages = 73728 B

__device__ __half g_Q[4 * NH * SEQ * DH];
__device__ __half g_K[4 * NH * SEQ * DH];
__device__ __half g_V[4 * NH * SEQ * DH];

__device__ __forceinline__ unsigned pack_h2(float a, float b) {
    __half2 h = __floats2half2_rn(a, b);
    return *reinterpret_cast<unsigned*>(&h);
}
__device__ __forceinline__ unsigned ex2h2(unsigned x) {
    unsigned y; asm("ex2.approx.f16x2 %0, %1;" : "=r"(y) : "r"(x)); return y;
}
__device__ __forceinline__ __half2 u2h(unsigned x) { return *reinterpret_cast<__half2*>(&x); }
__device__ __forceinline__ unsigned h2u(__half2 h) { return *reinterpret_cast<unsigned*>(&h); }

// ---------------- preprocess ----------------
__global__ void preprocess_kernel(
    const float* __restrict__ q_in, const float* __restrict__ k_in, const float* __restrict__ v_in,
    const float* __restrict__ wq, const float* __restrict__ bq,
    const float* __restrict__ wk, const float* __restrict__ bk,
    const float* __restrict__ wv, const float* __restrict__ bv,
    int total4)
{
    const float qs = 0.125f * 1.44269504088896340736f;
    int i4 = blockIdx.x * blockDim.x + threadIdx.x;
    if (i4 >= total4) return;
    int c4 = i4 & 63;
    int s  = (i4 >> 6) & (SEQ - 1);
    int b  = i4 >> 18;
    int c  = c4 * 4;
    int h  = c >> 6;
    int d  = c & 63;
    int in_idx  = (b * SEQ + s) * 256 + c;
    int out_idx = ((b * NH + h) * SEQ + s) * DH + d;

    float4 qv = *(const float4*)(q_in + in_idx);
    float4 kv = *(const float4*)(k_in + in_idx);
    float4 vv = *(const float4*)(v_in + in_idx);
    float4 w, bb; uint2 p;

    w = *(const float4*)(wq + c); bb = *(const float4*)(bq + c);
    p.x = pack_h2((qv.x * w.x + bb.x) * qs, (qv.y * w.y + bb.y) * qs);
    p.y = pack_h2((qv.z * w.z + bb.z) * qs, (qv.w * w.w + bb.w) * qs);
    *(uint2*)(g_Q + out_idx) = p;

    w = *(const float4*)(wk + c); bb = *(const float4*)(bk + c);
    p.x = pack_h2(kv.x * w.x + bb.x, kv.y * w.y + bb.y);
    p.y = pack_h2(kv.z * w.z + bb.z, kv.w * w.w + bb.w);
    *(uint2*)(g_K + out_idx) = p;

    w = *(const float4*)(wv + c); bb = *(const float4*)(bv + c);
    p.x = pack_h2(vv.x * w.x + bb.x, vv.y * w.y + bb.y);
    p.y = pack_h2(vv.z * w.z + bb.z, vv.w * w.w + bb.w);
    *(uint2*)(g_V + out_idx) = p;
}

// ---------------- mma / ldsm helpers ----------------
__device__ __forceinline__ void mma16816(float c[4], unsigned a0, unsigned a1, unsigned a2, unsigned a3,
                                         unsigned b0, unsigned b1) {
    asm volatile(
        "mma.sync.aligned.m16n8k16.row.col.f32.f16.f16.f32 "
        "{%0,%1,%2,%3},{%4,%5,%6,%7},{%8,%9},{%0,%1,%2,%3};\n"
        : "+f"(c[0]), "+f"(c[1]), "+f"(c[2]), "+f"(c[3])
        : "r"(a0), "r"(a1), "r"(a2), "r"(a3), "r"(b0), "r"(b1));
}
__device__ __forceinline__ void mma16816h(unsigned c[2], const unsigned a[4], unsigned b0, unsigned b1) {
    asm volatile(
        "mma.sync.aligned.m16n8k16.row.col.f16.f16.f16.f16 "
        "{%0,%1},{%2,%3,%4,%5},{%6,%7},{%0,%1};\n"
        : "+r"(c[0]), "+r"(c[1])
        : "r"(a[0]), "r"(a[1]), "r"(a[2]), "r"(a[3]), "r"(b0), "r"(b1));
}
__device__ __forceinline__ void ldsm_x4u(unsigned& r0, unsigned& r1, unsigned& r2, unsigned& r3, unsigned addr) {
    asm volatile("ldmatrix.sync.aligned.m8n8.x4.shared.b16 {%0,%1,%2,%3}, [%4];\n"
                 : "=r"(r0), "=r"(r1), "=r"(r2), "=r"(r3) : "r"(addr));
}
__device__ __forceinline__ void ldsm_x4tu(unsigned& r0, unsigned& r1, unsigned& r2, unsigned& r3, unsigned addr) {
    asm volatile("ldmatrix.sync.aligned.m8n8.x4.trans.shared.b16 {%0,%1,%2,%3}, [%4];\n"
                 : "=r"(r0), "=r"(r1), "=r"(r2), "=r"(r3) : "r"(addr));
}
__device__ __forceinline__ void cp16u(unsigned dst, const __half* src) {
    asm volatile("cp.async.cg.shared.global [%0], [%1], 16;\n" :: "r"(dst), "l"(src));
}

__global__ void __launch_bounds__(128, 3) attn_kernel(
    float* __restrict__ out, const float* __restrict__ wp, const float* __restrict__ bp)
{
    extern __shared__ __half smbuf[];
    __half* Ks = smbuf;                 // 2 stages
    __half* Vs = smbuf + 2 * TSZ;       // 2 stages
    const unsigned ks_u = (unsigned)__cvta_generic_to_shared(Ks);
    const unsigned vs_u = (unsigned)__cvta_generic_to_shared(Vs);

    const int tid  = threadIdx.x;
    const int w    = tid >> 5;
    const int lane = tid & 31;
    const int gid  = lane >> 2;
    const int tig  = lane & 3;
    const __half2 cl = __floats2half2_rn(14.0f, 14.0f);

    const int bh = blockIdx.y;
    const int b  = bh >> 2;
    const int h  = bh & 3;
    const int q0 = blockIdx.x * BM;

    const __half* Qg = g_Q + bh * (SEQ * DH);
    const __half* Kg = g_K + bh * (SEQ * DH);
    const __half* Vg = g_V + bh * (SEQ * DH);

    const unsigned kbase = ks_u + ((lane & 7) * KPAD + (lane >> 3) * 8) * 2;
    const unsigned vbase = vs_u + (lane * KPAD) * 2;

    auto fillK = [&](int f) {
        if (f >= NTILES) return;
        unsigned dst0 = ks_u + (f & 1) * STAGE_B;
        const __half* src = Kg + f * BN * DH;
        #pragma unroll
        for (int i = 0; i < 8; i++) {
            int idx = i * 128 + tid;
            int r = idx >> 3, c = idx & 7;
            cp16u(dst0 + (r * KPAD + c * 8) * 2, src + r * DH + c * 8);
        }
    };
    auto fillV = [&](int f) {
        if (f >= NTILES) return;
        unsigned dst0 = vs_u + (f & 1) * STAGE_B;
        const __half* src = Vg + f * BN * DH;
        #pragma unroll
        for (int i = 0; i < 8; i++) {
            int idx = i * 128 + tid;
            int r = idx >> 3, c = idx & 7;
            cp16u(dst0 + (r * KPAD + c * 8) * 2, src + r * DH + c * 8);
        }
    };

    fillK(0); fillV(0); asm volatile("cp.async.commit_group;\n");

    // Q fragments: 1 m-tile (16 rows)
    unsigned qa[4][4];
    {
        const __half* qrow0 = Qg + (q0 + w * 16 + gid) * DH;
        const __half* qrow1 = qrow0 + 8 * DH;
        #pragma unroll
        for (int kk = 0; kk < 4; kk++) {
            int c0 = kk * 16 + tig * 2;
            qa[kk][0] = *(const unsigned*)(qrow0 + c0);
            qa[kk][1] = *(const unsigned*)(qrow1 + c0);
            qa[kk][2] = *(const unsigned*)(qrow0 + c0 + 8);
            qa[kk][3] = *(const unsigned*)(qrow1 + c0 + 8);
        }
    }

    float o[8][4];
    #pragma unroll
    for (int j = 0; j < 8; j++)
        { o[j][0]=0.f; o[j][1]=0.f; o[j][2]=0.f; o[j][3]=0.f; }
    __half2 mh0, mh1;
    float l[2] = {0.f, 0.f};

    #pragma unroll 1
    for (int t = 0; t < NTILES; t++) {
        asm volatile("cp.async.wait_group 0;\n");
        __syncthreads();
        fillK(t + 1);
        fillV(t + 1);
        asm volatile("cp.async.commit_group;\n");

        const unsigned kst = kbase + (t & 1) * STAGE_B;
        const unsigned vst = vbase + (t & 1) * STAGE_B;

        // ---- S = Q K^T (f16 accum), depth-1 ldsm lookahead ----
        unsigned s[16][2];
        #pragma unroll
        for (int j = 0; j < 16; j++) { s[j][0] = 0u; s[j][1] = 0u; }
        {
            unsigned bf[2][4];
            ldsm_x4u(bf[0][0], bf[0][1], bf[0][2], bf[0][3], kst);   // (j=0, kd=0)
            #pragma unroll
            for (int i = 0; i < 32; i++) {
                const int cb = i & 1;
                if (i < 31) {
                    const int jn = (i + 1) >> 1, kdn = (i + 1) & 1, nb = (i + 1) & 1;
                    ldsm_x4u(bf[nb][0], bf[nb][1], bf[nb][2], bf[nb][3],
                             kst + jn * (8 * KPAD * 2) + kdn * 64);
                }
                const int j = i >> 1, kd = i & 1;
                mma16816h(s[j], qa[2 * kd],     bf[cb][0], bf[cb][1]);
                mma16816h(s[j], qa[2 * kd + 1], bf[cb][2], bf[cb][3]);
            }
        }

        // ---- tile 0: freeze per-row reference max ----
        if (t == 0) {
            __half2 h0 = u2h(s[0][0]), h1 = u2h(s[0][1]);
            #pragma unroll
            for (int j = 1; j < 16; j++) {
                h0 = __hmax2(h0, u2h(s[j][0]));
                h1 = __hmax2(h1, u2h(s[j][1]));
            }
            float rm0 = __half2float(__hmax(__low2half(h0), __high2half(h0)));
            float rm1 = __half2float(__hmax(__low2half(h1), __high2half(h1)));
            rm0 = fmaxf(rm0, __shfl_xor_sync(0xffffffffu, rm0, 1));
            rm0 = fmaxf(rm0, __shfl_xor_sync(0xffffffffu, rm0, 2));
            rm1 = fmaxf(rm1, __shfl_xor_sync(0xffffffffu, rm1, 1));
            rm1 = fmaxf(rm1, __shfl_xor_sync(0xffffffffu, rm1, 2));
            mh0 = __float2half2_rn(rm0 + 2.0f);
            mh1 = __float2half2_rn(rm1 + 2.0f);
        }

        // ---- softmax in place: P = exp2(min(S - m, 14)) ----
        #pragma unroll
        for (int j = 0; j < 16; j++) {
            s[j][0] = ex2h2(h2u(__hmin2(__hsub2(u2h(s[j][0]), mh0), cl)));
            s[j][1] = ex2h2(h2u(__hmin2(__hsub2(u2h(s[j][1]), mh1), cl)));
        }
        #pragma unroll
        for (int blk = 0; blk < 2; blk++) {
            int j0 = blk * 8;
            __half2 a0 = __hadd2(u2h(s[j0 + 0][0]), u2h(s[j0 + 1][0]));
            __half2 a1 = __hadd2(u2h(s[j0 + 2][0]), u2h(s[j0 + 3][0]));
            __half2 a2 = __hadd2(u2h(s[j0 + 4][0]), u2h(s[j0 + 5][0]));
            __half2 a3 = __hadd2(u2h(s[j0 + 6][0]), u2h(s[j0 + 7][0]));
            float2 f0 = __half22float2(__hadd2(a0, a1));
            float2 f1 = __half22float2(__hadd2(a2, a3));
            l[0] += (f0.x + f0.y) + (f1.x + f1.y);
            __half2 b0 = __hadd2(u2h(s[j0 + 0][1]), u2h(s[j0 + 1][1]));
            __half2 b1 = __hadd2(u2h(s[j0 + 2][1]), u2h(s[j0 + 3][1]));
            __half2 b2 = __hadd2(u2h(s[j0 + 4][1]), u2h(s[j0 + 5][1]));
            __half2 b3 = __hadd2(u2h(s[j0 + 6][1]), u2h(s[j0 + 7][1]));
            float2 g0 = __half22float2(__hadd2(b0, b1));
            float2 g1 = __half22float2(__hadd2(b2, b3));
            l[1] += (g0.x + g0.y) + (g1.x + g1.y);
        }

        // ---- O += P V (f32 accum), depth-1 ldsm lookahead over (kk2, jd) ----
        {
            unsigned bv[2][4];
            ldsm_x4tu(bv[0][0], bv[0][1], bv[0][2], bv[0][3], vst);   // (kk2=0, jd=0)
            #pragma unroll
            for (int i = 0; i < 32; i++) {
                const int cb = i & 1;
                if (i < 31) {
                    const int kk2n = (i + 1) >> 3, jdn = (i + 1) & 7, nb = (i + 1) & 1;
                    ldsm_x4tu(bv[nb][0], bv[nb][1], bv[nb][2], bv[nb][3],
                              vst + kk2n * (32 * KPAD * 2) + jdn * 16);
                }
                const int kk2 = i >> 3, jd = i & 7;
                const int k0 = 4 * kk2, k1 = 4 * kk2 + 2;
                mma16816(o[jd], s[k0][0], s[k0][1], s[k0 + 1][0], s[k0 + 1][1], bv[cb][0], bv[cb][1]);
                mma16816(o[jd], s[k1][0], s[k1][1], s[k1 + 1][0], s[k1 + 1][1], bv[cb][2], bv[cb][3]);
            }
        }
    }

    // ---- epilogue: reduce l across quad, normalize, output affine ----
    #pragma unroll
    for (int i = 0; i < 2; i++) {
        l[i] += __shfl_xor_sync(0xffffffffu, l[i], 1);
        l[i] += __shfl_xor_sync(0xffffffffu, l[i], 2);
    }
    {
        float inv0 = 1.f / l[0], inv1 = 1.f / l[1];
        int row0 = q0 + w * 16 + gid;
        float* out0 = out + (b * SEQ + row0) * 256 + h * 64;
        float* out1 = out0 + 8 * 256;
        #pragma unroll
        for (int jd = 0; jd < 8; jd++) {
            int c = jd * 8 + tig * 2;
            float2 w2 = *(const float2*)(wp + h * 64 + c);
            float2 b2 = *(const float2*)(bp + h * 64 + c);
            float2 r0, r1;
            r0.x = o[jd][0] * inv0 * w2.x + b2.x;
            r0.y = o[jd][1] * inv0 * w2.y + b2.y;
            r1.x = o[jd][2] * inv1 * w2.x + b2.x;
            r1.y = o[jd][3] * inv1 * w2.y + b2.y;
            *(float2*)(out0 + c) = r0;
            *(float2*)(out1 + c) = r1;
        }
    }
}

// ---------------- launch ----------------
extern "C" void kernel_launch(void* const* d_in, const int* in_sizes, int n_in,
                              void* d_out, int out_size)
{
    const float* q_in = (const float*)d_in[0];
    const float* k_in = (const float*)d_in[1];
    const float* v_in = (const float*)d_in[2];
    const float* wq = (const float*)d_in[3];
    const float* bq = (const float*)d_in[4];
    const float* wk = (const float*)d_in[5];
    const float* bk = (const float*)d_in[6];
    const float* wv = (const float*)d_in[7];
    const float* bv = (const float*)d_in[8];
    const float* wp = (const float*)d_in[9];
    const float* bp = (const float*)d_in[10];

    int B = in_sizes[0] / (SEQ * 256);
    int total4 = B * SEQ * 64;

    cudaFuncSetAttribute(attn_kernel, cudaFuncAttributeMaxDynamicSharedMemorySize, SMEM_BYTES);

    preprocess_kernel<<<(total4 + 255) / 256, 256>>>(
        q_in, k_in, v_in, wq, bq, wk, bk, wv, bv, total4);

    dim3 grid(SEQ / BM, B * NH);
    attn_kernel<<<grid, 128, SMEM_BYTES>>>((float*)d_out, wp, bp);
}

// round 16
// speedup vs baseline: 1.0623x; 1.0623x over previous
#include <cuda_runtime.h>
#include <cuda_fp16.h>
#include <math_constants.h>

#define SEQ 4096
#define DH 64
#define NH 4
#define BM 128          // 4 warps x 32 rows
#define BN 128          // keys per tile
#define NTILES (SEQ / BN)              // 32
#define KPAD 72
#define TSZ (BN * KPAD)                // halves per stage (9216)
#define STAGE_B (TSZ * 2)              // 18432 B
#define SMEM_BYTES (6 * STAGE_B)       // 3 K + 3 V stages = 110592 B

__device__ __half g_Q[4 * NH * SEQ * DH];
__device__ __half g_K[4 * NH * SEQ * DH];
__device__ __half g_V[4 * NH * SEQ * DH];

__device__ __forceinline__ unsigned pack_h2(float a, float b) {
    __half2 h = __floats2half2_rn(a, b);
    return *reinterpret_cast<unsigned*>(&h);
}
__device__ __forceinline__ unsigned ex2h2(unsigned x) {
    unsigned y; asm("ex2.approx.f16x2 %0, %1;" : "=r"(y) : "r"(x)); return y;
}
__device__ __forceinline__ __half2 u2h(unsigned x) { return *reinterpret_cast<__half2*>(&x); }
__device__ __forceinline__ unsigned h2u(__half2 h) { return *reinterpret_cast<unsigned*>(&h); }

// ---------------- preprocess ----------------
__global__ void preprocess_kernel(
    const float* __restrict__ q_in, const float* __restrict__ k_in, const float* __restrict__ v_in,
    const float* __restrict__ wq, const float* __restrict__ bq,
    const float* __restrict__ wk, const float* __restrict__ bk,
    const float* __restrict__ wv, const float* __restrict__ bv,
    int total4)
{
    const float qs = 0.125f * 1.44269504088896340736f;
    int i4 = blockIdx.x * blockDim.x + threadIdx.x;
    if (i4 >= total4) return;
    int c4 = i4 & 63;
    int s  = (i4 >> 6) & (SEQ - 1);
    int b  = i4 >> 18;
    int c  = c4 * 4;
    int h  = c >> 6;
    int d  = c & 63;
    int in_idx  = (b * SEQ + s) * 256 + c;
    int out_idx = ((b * NH + h) * SEQ + s) * DH + d;

    float4 qv = *(const float4*)(q_in + in_idx);
    float4 kv = *(const float4*)(k_in + in_idx);
    float4 vv = *(const float4*)(v_in + in_idx);
    float4 w, bb; uint2 p;

    w = *(const float4*)(wq + c); bb = *(const float4*)(bq + c);
    p.x = pack_h2((qv.x * w.x + bb.x) * qs, (qv.y * w.y + bb.y) * qs);
    p.y = pack_h2((qv.z * w.z + bb.z) * qs, (qv.w * w.w + bb.w) * qs);
    *(uint2*)(g_Q + out_idx) = p;

    w = *(const float4*)(wk + c); bb = *(const float4*)(bk + c);
    p.x = pack_h2(kv.x * w.x + bb.x, kv.y * w.y + bb.y);
    p.y = pack_h2(kv.z * w.z + bb.z, kv.w * w.w + bb.w);
    *(uint2*)(g_K + out_idx) = p;

    w = *(const float4*)(wv + c); bb = *(const float4*)(bv + c);
    p.x = pack_h2(vv.x * w.x + bb.x, vv.y * w.y + bb.y);
    p.y = pack_h2(vv.z * w.z + bb.z, vv.w * w.w + bb.w);
    *(uint2*)(g_V + out_idx) = p;
}

// ---------------- mma / ldsm helpers ----------------
__device__ __forceinline__ void mma16816(float c[4], unsigned a0, unsigned a1, unsigned a2, unsigned a3,
                                         unsigned b0, unsigned b1) {
    asm volatile(
        "mma.sync.aligned.m16n8k16.row.col.f32.f16.f16.f32 "
        "{%0,%1,%2,%3},{%4,%5,%6,%7},{%8,%9},{%0,%1,%2,%3};\n"
        : "+f"(c[0]), "+f"(c[1]), "+f"(c[2]), "+f"(c[3])
        : "r"(a0), "r"(a1), "r"(a2), "r"(a3), "r"(b0), "r"(b1));
}
__device__ __forceinline__ void mma16816h(unsigned c[2], const unsigned a[4], unsigned b0, unsigned b1) {
    asm volatile(
        "mma.sync.aligned.m16n8k16.row.col.f16.f16.f16.f16 "
        "{%0,%1},{%2,%3,%4,%5},{%6,%7},{%0,%1};\n"
        : "+r"(c[0]), "+r"(c[1])
        : "r"(a[0]), "r"(a[1]), "r"(a[2]), "r"(a[3]), "r"(b0), "r"(b1));
}
// first k-step: C = {z,z} (zero), D overwritten — removes s pre-zeroing
__device__ __forceinline__ void mma16816h_zc(unsigned c[2], const unsigned a[4], unsigned b0, unsigned b1,
                                             unsigned z) {
    asm volatile(
        "mma.sync.aligned.m16n8k16.row.col.f16.f16.f16.f16 "
        "{%0,%1},{%2,%3,%4,%5},{%6,%7},{%8,%8};\n"
        : "=r"(c[0]), "=r"(c[1])
        : "r"(a[0]), "r"(a[1]), "r"(a[2]), "r"(a[3]), "r"(b0), "r"(b1), "r"(z));
}
__device__ __forceinline__ void ldsm_x4u(unsigned& r0, unsigned& r1, unsigned& r2, unsigned& r3, unsigned addr) {
    asm volatile("ldmatrix.sync.aligned.m8n8.x4.shared.b16 {%0,%1,%2,%3}, [%4];\n"
                 : "=r"(r0), "=r"(r1), "=r"(r2), "=r"(r3) : "r"(addr));
}
__device__ __forceinline__ void ldsm_x4tu(unsigned& r0, unsigned& r1, unsigned& r2, unsigned& r3, unsigned addr) {
    asm volatile("ldmatrix.sync.aligned.m8n8.x4.trans.shared.b16 {%0,%1,%2,%3}, [%4];\n"
                 : "=r"(r0), "=r"(r1), "=r"(r2), "=r"(r3) : "r"(addr));
}
__device__ __forceinline__ void cp16u(unsigned dst, const __half* src) {
    asm volatile("cp.async.cg.shared.global [%0], [%1], 16;\n" :: "r"(dst), "l"(src));
}

__global__ void __launch_bounds__(128, 2) attn_kernel(
    float* __restrict__ out, const float* __restrict__ wp, const float* __restrict__ bp)
{
    extern __shared__ __half smbuf[];
    __half* Ks = smbuf;                 // 3 stages
    __half* Vs = smbuf + 3 * TSZ;       // 3 stages
    const unsigned ks_u = (unsigned)__cvta_generic_to_shared(Ks);
    const unsigned vs_u = (unsigned)__cvta_generic_to_shared(Vs);

    const int tid  = threadIdx.x;
    const int w    = tid >> 5;
    const int lane = tid & 31;
    const int gid  = lane >> 2;
    const int tig  = lane & 3;
    const __half2 cl = __floats2half2_rn(14.0f, 14.0f);

    const int bh = blockIdx.y;
    const int b  = bh >> 2;
    const int h  = bh & 3;
    const int q0 = blockIdx.x * BM;

    const __half* Qg = g_Q + bh * (SEQ * DH);
    const __half* Kg = g_K + bh * (SEQ * DH);
    const __half* Vg = g_V + bh * (SEQ * DH);

    const unsigned kbase = ks_u + ((lane & 7) * KPAD + (lane >> 3) * 8) * 2;
    const unsigned vbase = vs_u + (lane * KPAD) * 2;

    auto fillK = [&](int f) {
        if (f >= NTILES) return;
        unsigned dst0 = ks_u + (f % 3) * STAGE_B;
        const __half* src = Kg + f * BN * DH;
        #pragma unroll
        for (int i = 0; i < 8; i++) {
            int idx = i * 128 + tid;
            int r = idx >> 3, c = idx & 7;
            cp16u(dst0 + (r * KPAD + c * 8) * 2, src + r * DH + c * 8);
        }
    };
    auto fillV = [&](int f) {
        if (f >= NTILES) return;
        unsigned dst0 = vs_u + (f % 3) * STAGE_B;
        const __half* src = Vg + f * BN * DH;
        #pragma unroll
        for (int i = 0; i < 8; i++) {
            int idx = i * 128 + tid;
            int r = idx >> 3, c = idx & 7;
            cp16u(dst0 + (r * KPAD + c * 8) * 2, src + r * DH + c * 8);
        }
    };

    fillK(0); fillV(0); asm volatile("cp.async.commit_group;\n");
    fillK(1); fillV(1); asm volatile("cp.async.commit_group;\n");

    unsigned qa[2][4][4];
    #pragma unroll
    for (int m = 0; m < 2; m++) {
        const __half* qrow0 = Qg + (q0 + w * 32 + m * 16 + gid) * DH;
        const __half* qrow1 = qrow0 + 8 * DH;
        #pragma unroll
        for (int kk = 0; kk < 4; kk++) {
            int c0 = kk * 16 + tig * 2;
            qa[m][kk][0] = *(const unsigned*)(qrow0 + c0);
            qa[m][kk][1] = *(const unsigned*)(qrow1 + c0);
            qa[m][kk][2] = *(const unsigned*)(qrow0 + c0 + 8);
            qa[m][kk][3] = *(const unsigned*)(qrow1 + c0 + 8);
        }
    }

    float o[2][8][4];
    #pragma unroll
    for (int m = 0; m < 2; m++)
        #pragma unroll
        for (int j = 0; j < 8; j++)
            { o[m][j][0]=0.f; o[m][j][1]=0.f; o[m][j][2]=0.f; o[m][j][3]=0.f; }
    __half2 mh[4];
    float l[4] = {0.f, 0.f, 0.f, 0.f};
    const unsigned zr = 0u;

    #pragma unroll 1
    for (int t = 0; t < NTILES; t++) {
        if (t + 1 < NTILES) asm volatile("cp.async.wait_group 1;\n");
        else                asm volatile("cp.async.wait_group 0;\n");
        __syncthreads();
        fillK(t + 2);
        fillV(t + 2);
        asm volatile("cp.async.commit_group;\n");

        const unsigned kst = kbase + (t % 3) * STAGE_B;
        const unsigned vst = vbase + (t % 3) * STAGE_B;

        // ---- S = Q K^T (f16 accum), depth-1 ldsm lookahead, zero-C first k-step ----
        unsigned s[2][16][2];
        {
            unsigned bf[2][4];
            ldsm_x4u(bf[0][0], bf[0][1], bf[0][2], bf[0][3], kst);   // (j=0, kd=0)
            #pragma unroll
            for (int i = 0; i < 32; i++) {
                const int cb = i & 1;
                if (i < 31) {
                    const int jn = (i + 1) >> 1, kdn = (i + 1) & 1, nb = (i + 1) & 1;
                    ldsm_x4u(bf[nb][0], bf[nb][1], bf[nb][2], bf[nb][3],
                             kst + jn * (8 * KPAD * 2) + kdn * 64);
                }
                const int j = i >> 1, kd = i & 1;
                if (kd == 0) {
                    mma16816h_zc(s[0][j], qa[0][0], bf[cb][0], bf[cb][1], zr);
                    mma16816h   (s[0][j], qa[0][1], bf[cb][2], bf[cb][3]);
                    mma16816h_zc(s[1][j], qa[1][0], bf[cb][0], bf[cb][1], zr);
                    mma16816h   (s[1][j], qa[1][1], bf[cb][2], bf[cb][3]);
                } else {
                    mma16816h(s[0][j], qa[0][2], bf[cb][0], bf[cb][1]);
                    mma16816h(s[0][j], qa[0][3], bf[cb][2], bf[cb][3]);
                    mma16816h(s[1][j], qa[1][2], bf[cb][0], bf[cb][1]);
                    mma16816h(s[1][j], qa[1][3], bf[cb][2], bf[cb][3]);
                }
            }
        }

        // ---- hoist first V ldsm: loads during the MUFU chain below ----
        unsigned bv[2][4];
        ldsm_x4tu(bv[0][0], bv[0][1], bv[0][2], bv[0][3], vst);   // (kk2=0, jd=0)

        // ---- tile 0: freeze per-row reference max ----
        if (t == 0) {
            #pragma unroll
            for (int m = 0; m < 2; m++) {
                __half2 h0 = u2h(s[m][0][0]), h1 = u2h(s[m][0][1]);
                #pragma unroll
                for (int j = 1; j < 16; j++) {
                    h0 = __hmax2(h0, u2h(s[m][j][0]));
                    h1 = __hmax2(h1, u2h(s[m][j][1]));
                }
                float rm0 = __half2float(__hmax(__low2half(h0), __high2half(h0)));
                float rm1 = __half2float(__hmax(__low2half(h1), __high2half(h1)));
                rm0 = fmaxf(rm0, __shfl_xor_sync(0xffffffffu, rm0, 1));
                rm0 = fmaxf(rm0, __shfl_xor_sync(0xffffffffu, rm0, 2));
                rm1 = fmaxf(rm1, __shfl_xor_sync(0xffffffffu, rm1, 1));
                rm1 = fmaxf(rm1, __shfl_xor_sync(0xffffffffu, rm1, 2));
                mh[2 * m]     = __float2half2_rn(rm0 + 2.0f);
                mh[2 * m + 1] = __float2half2_rn(rm1 + 2.0f);
            }
        }

        // ---- softmax in place: P = exp2(min(S - m, 14)) ----
        #pragma unroll
        for (int m = 0; m < 2; m++) {
            #pragma unroll
            for (int j = 0; j < 16; j++) {
                s[m][j][0] = ex2h2(h2u(__hmin2(__hsub2(u2h(s[m][j][0]), mh[2 * m]),     cl)));
                s[m][j][1] = ex2h2(h2u(__hmin2(__hsub2(u2h(s[m][j][1]), mh[2 * m + 1]), cl)));
            }
            #pragma unroll
            for (int blk = 0; blk < 2; blk++) {
                int j0 = blk * 8;
                __half2 a0 = __hadd2(u2h(s[m][j0 + 0][0]), u2h(s[m][j0 + 1][0]));
                __half2 a1 = __hadd2(u2h(s[m][j0 + 2][0]), u2h(s[m][j0 + 3][0]));
                __half2 a2 = __hadd2(u2h(s[m][j0 + 4][0]), u2h(s[m][j0 + 5][0]));
                __half2 a3 = __hadd2(u2h(s[m][j0 + 6][0]), u2h(s[m][j0 + 7][0]));
                float2 f0 = __half22float2(__hadd2(a0, a1));
                float2 f1 = __half22float2(__hadd2(a2, a3));
                l[2 * m] += (f0.x + f0.y) + (f1.x + f1.y);
                __half2 b0 = __hadd2(u2h(s[m][j0 + 0][1]), u2h(s[m][j0 + 1][1]));
                __half2 b1 = __hadd2(u2h(s[m][j0 + 2][1]), u2h(s[m][j0 + 3][1]));
                __half2 b2 = __hadd2(u2h(s[m][j0 + 4][1]), u2h(s[m][j0 + 5][1]));
                __half2 b3 = __hadd2(u2h(s[m][j0 + 6][1]), u2h(s[m][j0 + 7][1]));
                float2 g0 = __half22float2(__hadd2(b0, b1));
                float2 g1 = __half22float2(__hadd2(b2, b3));
                l[2 * m + 1] += (g0.x + g0.y) + (g1.x + g1.y);
            }
        }

        // ---- O += P V (f32 accum), depth-1 ldsm lookahead over (kk2, jd) ----
        {
            #pragma unroll
            for (int i = 0; i < 32; i++) {
                const int cb = i & 1;
                if (i < 31) {
                    const int kk2n = (i + 1) >> 3, jdn = (i + 1) & 7, nb = (i + 1) & 1;
                    ldsm_x4tu(bv[nb][0], bv[nb][1], bv[nb][2], bv[nb][3],
                              vst + kk2n * (32 * KPAD * 2) + jdn * 16);
                }
                const int kk2 = i >> 3, jd = i & 7;
                const int k0 = 4 * kk2, k1 = 4 * kk2 + 2;
                mma16816(o[0][jd], s[0][k0][0], s[0][k0][1], s[0][k0 + 1][0], s[0][k0 + 1][1], bv[cb][0], bv[cb][1]);
                mma16816(o[0][jd], s[0][k1][0], s[0][k1][1], s[0][k1 + 1][0], s[0][k1 + 1][1], bv[cb][2], bv[cb][3]);
                mma16816(o[1][jd], s[1][k0][0], s[1][k0][1], s[1][k0 + 1][0], s[1][k0 + 1][1], bv[cb][0], bv[cb][1]);
                mma16816(o[1][jd], s[1][k1][0], s[1][k1][1], s[1][k1 + 1][0], s[1][k1 + 1][1], bv[cb][2], bv[cb][3]);
            }
        }
    }

    // ---- epilogue: reduce l across quad, normalize, output affine ----
    #pragma unroll
    for (int i = 0; i < 4; i++) {
        l[i] += __shfl_xor_sync(0xffffffffu, l[i], 1);
        l[i] += __shfl_xor_sync(0xffffffffu, l[i], 2);
    }
    #pragma unroll
    for (int m = 0; m < 2; m++) {
        float inv0 = 1.f / l[2 * m], inv1 = 1.f / l[2 * m + 1];
        int row0 = q0 + w * 32 + m * 16 + gid;
        float* out0 = out + (b * SEQ + row0) * 256 + h * 64;
        float* out1 = out0 + 8 * 256;
        #pragma unroll
        for (int jd = 0; jd < 8; jd++) {
            int c = jd * 8 + tig * 2;
            float2 w2 = *(const float2*)(wp + h * 64 + c);
            float2 b2 = *(const float2*)(bp + h * 64 + c);
            float2 r0, r1;
            r0.x = o[m][jd][0] * inv0 * w2.x + b2.x;
            r0.y = o[m][jd][1] * inv0 * w2.y + b2.y;
            r1.x = o[m][jd][2] * inv1 * w2.x + b2.x;
            r1.y = o[m][jd][3] * inv1 * w2.y + b2.y;
            *(float2*)(out0 + c) = r0;
            *(float2*)(out1 + c) = r1;
        }
    }
}

// ---------------- launch ----------------
extern "C" void kernel_launch(void* const* d_in, const int* in_sizes, int n_in,
                              void* d_out, int out_size)
{
    const float* q_in = (const float*)d_in[0];
    const float* k_in = (const float*)d_in[1];
    const float* v_in = (const float*)d_in[2];
    const float* wq = (const float*)d_in[3];
    const float* bq = (const float*)d_in[4];
    const float* wk = (const float*)d_in[5];
    const float* bk = (const float*)d_in[6];
    const float* wv = (const float*)d_in[7];
    const float* bv = (const float*)d_in[8];
    const float* wp = (const float*)d_in[9];
    const float* bp = (const float*)d_in[10];

    int B = in_sizes[0] / (SEQ * 256);
    int total4 = B * SEQ * 64;

    cudaFuncSetAttribute(attn_kernel, cudaFuncAttributeMaxDynamicSharedMemorySize, SMEM_BYTES);

    preprocess_kernel<<<(total4 + 255) / 256, 256>>>(
        q_in, k_in, v_in, wq, bq, wk, bk, wv, bv, total4);

    dim3 grid(SEQ / BM, B * NH);
    attn_kernel<<<grid, 128, SMEM_BYTES>>>((float*)d_out, wp, bp);
}